// round 15
// baseline (speedup 1.0000x reference)
#include <cuda_runtime.h>
#include <cuda_fp16.h>
#include <cstdint>

#define N_ 4
#define CI_ 64
#define CO_ 64
#define L_ 1024
#define V_ 25
#define P_ 3
#define VP_ 32
#define KW_ 9
#define K2_ 192
#define LT_ 4

// ---------------- scratch (__device__ globals) ----------------
__device__ __align__(16) __half g_u2h[N_*L_*V_*CO_];  // [n][l][w25][c] pre-BN (fp16)
__device__ float g_sum[CO_], g_sumsq[CO_];            // zero-init; k3z re-zeroes
__device__ float g_scale[CO_], g_shift[CO_];

// ---------------- PTX primitives ----------------
__device__ __forceinline__ uint32_t smem_u32(const void* p) {
    uint32_t a;
    asm("{ .reg .u64 t; cvta.to.shared.u64 t, %1; cvt.u32.u64 %0, t; }" : "=r"(a) : "l"(p));
    return a;
}
#define LDSM4(r, addr) \
    asm volatile("ldmatrix.sync.aligned.m8n8.x4.shared.b16 {%0,%1,%2,%3}, [%4];" \
        : "=r"((r)[0]), "=r"((r)[1]), "=r"((r)[2]), "=r"((r)[3]) : "r"(addr))
#define LDSM4T(r, addr) \
    asm volatile("ldmatrix.sync.aligned.m8n8.x4.trans.shared.b16 {%0,%1,%2,%3}, [%4];" \
        : "=r"((r)[0]), "=r"((r)[1]), "=r"((r)[2]), "=r"((r)[3]) : "r"(addr))
#define MMA16816(d, a, b0, b1) \
    asm volatile("mma.sync.aligned.m16n8k16.row.col.f32.f16.f16.f32 " \
        "{%0,%1,%2,%3}, {%4,%5,%6,%7}, {%8,%9}, {%0,%1,%2,%3};" \
        : "+f"((d)[0]), "+f"((d)[1]), "+f"((d)[2]), "+f"((d)[3]) \
        : "r"((a)[0]), "r"((a)[1]), "r"((a)[2]), "r"((a)[3]), "r"(b0), "r"(b1))

// ---------------- k2: in-block weight fold + presum + double fp16 GEMM ----------------
// byte offsets into dynamic smem
#define SB_XS 0                         // half [256(lt,ci)][40v]    20480
#define SB_T  20480                     // half [192k][40w]          15360
#define SB_AE 35840                     // half [96(p,v)][40w]        7680
#define SB_U  43520                     // f32 2kh x [32w][68 c-ld]  17408
#define SB_BF 60928                     // f32 [32w][64c]             8192
#define SB_ST 69120                     // f32 stats 128               512
#define SB_CA 69632                     // f32 colA [96]               512 (pad)
#define SB_TOTAL 70144                  // 68.5 KB -> 3 blocks/SM
// W2 staging (transient): half [64c][200k] = 25600 B over [0, 25600)

__global__ void __launch_bounds__(256, 3) k2_fused(const float* __restrict__ x,
                                                   const float* __restrict__ A,
                                                   const float* __restrict__ edge,
                                                   const float* __restrict__ cw,
                                                   const float* __restrict__ cb) {
    extern __shared__ char sm[];
    const uint32_t sbase = smem_u32(sm);
    int tid = threadIdx.x, ww = tid >> 5, lane = tid & 31;
    int n = blockIdx.y, l0 = blockIdx.x * LT_;
    const int group = lane >> 2, tq = lane & 3;

    const uint32_t ldsm40  = ((lane & 7) + ((lane >> 3) & 1) * 8) * 80
                           + ((lane >> 4) & 1) * 16;
    const uint32_t ldsm200 = ((lane & 7) + ((lane >> 3) & 1) * 8) * 400
                           + ((lane >> 4) & 1) * 16;

    // ---- phase 0: fold W2 -> staging, fold Ae -> SB_AE, zero stats ----
    {
        __half* w2s = (__half*)sm;                     // [64c][200k]
        for (int i = tid; i < 64*200; i += 256) {
            int c = i / 200, k = i % 200;
            float val = 0.f;
            if (k < K2_) { int p = k >> 6, ci = k & 63; val = cw[(p*CO_ + c)*CI_ + ci]; }
            w2s[i] = __float2half(val);
        }
        __half* ae = (__half*)(sm + SB_AE);            // [96(p,v)][40w]
        for (int i = tid; i < 96*40; i += 256) {
            int row = i / 40, w = i % 40, p = row >> 5, v = row & 31;
            float val = 0.f;
            if (v < V_ && w < V_) { int j = (p*V_ + v)*V_ + w; val = A[j]*edge[j]; }
            ae[i] = __float2half(val);
        }
        float* st = (float*)(sm + SB_ST);
        if (tid < 128) st[tid] = 0.f;
    }
    __syncthreads();

    // ---- phase 1: wf fragment cache (from staging) + colA reduction ----
    const int r_s2 = ww & 3;
    const int kh   = ww >> 2;
    uint32_t wf[6][4];
    #pragma unroll
    for (int i = 0; i < 6; i++)
        LDSM4(wf[i], sbase + (uint32_t)((r_s2*16)*200 + (kh*6 + i)*16)*2 + ldsm200);
    {   // colA[p*32+w] = sum_v Ae[p][v][w]
        float* colA = (float*)(sm + SB_CA);
        const __half* ae = (const __half*)(sm + SB_AE);
        if (tid < 96) {
            int p = tid >> 5, w = tid & 31;
            float s = 0.f;
            if (w < V_)
                for (int v = 0; v < V_; v++) s += __half2float(ae[(p*32 + v)*40 + w]);
            colA[tid] = s;
        }
    }
    __syncthreads();                    // staging free; colA ready

    // ---- phase 2: BF from colA/cb + fused temporal presum -> XS ----
    {
        float* BFw = (float*)(sm + SB_BF);
        const float* colA = (const float*)(sm + SB_CA);
        for (int i = tid; i < VP_*CO_; i += 256) {
            int w = i >> 6, c = i & 63;
            float s = 0.f;
            #pragma unroll
            for (int p = 0; p < P_; p++) s += __ldg(&cb[p*CO_ + c]) * colA[p*32 + w];
            BFw[i] = s;
        }
    }
    __half* xs = (__half*)(sm + SB_XS);
    for (int it = 0; it < 8; it++) {
        int pair = tid + it*256;
        int ci = pair >> 5, v = pair & 31;
        if (v >= V_) {
            #pragma unroll
            for (int j = 0; j < LT_; j++) xs[(j*64 + ci)*40 + v] = __float2half(0.f);
            continue;
        }
        const float* xb = x + ((size_t)(n*CI_ + ci)*L_)*V_ + v;
        float vals[KW_ - 1 + LT_];
        #pragma unroll
        for (int i = 0; i < KW_ - 1 + LT_; i++) {
            int l = l0 - (KW_ - 1) + i;
            vals[i] = (l >= 0) ? xb[(size_t)l*V_] : 0.f;
        }
        float s = 0.f;
        #pragma unroll
        for (int i = 0; i < KW_ - 1; i++) s += vals[i];
        #pragma unroll
        for (int j = 0; j < LT_; j++) {
            s += vals[j + KW_ - 1];
            xs[(j*64 + ci)*40 + v] = __float2half(s);
            s -= vals[j];
        }
    }
    __syncthreads();

    const int myc = tid & 63;
    float csum = 0.f, csum2 = 0.f;
    float* Uf = (float*)(sm + SB_U);
    const float* BF = (const float*)(sm + SB_BF);

    for (int lt = 0; lt < LT_; lt++) {
        // ---- stage 1: T[(p*64+ci)][w] = xs_lt[ci][v] * Ae_p[v][w] ----
        {
            int ct = ww & 3, h = ww >> 2;
            uint32_t a[2][4];
            #pragma unroll
            for (int ks = 0; ks < 2; ks++)
                LDSM4(a[ks], sbase + SB_XS
                      + (uint32_t)((lt*64 + ct*16)*40 + ks*16)*2 + ldsm40);
            #pragma unroll
            for (int q = 0; q < 3; q++) {
                int idx = h*3 + q, p = idx >> 1, wt = idx & 1;
                float d[2][4] = {{0.f,0.f,0.f,0.f},{0.f,0.f,0.f,0.f}};
                #pragma unroll
                for (int ks = 0; ks < 2; ks++) {
                    uint32_t b[4];
                    LDSM4T(b, sbase + SB_AE
                           + (uint32_t)((p*32 + ks*16)*40 + wt*16)*2 + ldsm40);
                    MMA16816(d[0], a[ks], b[0], b[1]);
                    MMA16816(d[1], a[ks], b[2], b[3]);
                }
                #pragma unroll
                for (int j = 0; j < 2; j++) {
                    int wcol = wt*16 + j*8 + tq*2;
                    int row  = p*64 + ct*16 + group;
                    *(__half2*)(sm + SB_T + (row*40 + wcol)*2)
                        = __floats2half2_rn(d[j][0], d[j][1]);
                    *(__half2*)(sm + SB_T + ((row + 8)*40 + wcol)*2)
                        = __floats2half2_rn(d[j][2], d[j][3]);
                }
            }
        }
        __syncthreads();

        // ---- stage 2: U_kh[c][w] = sum_{k in half} W2[c][k] * T[k][w] ----
        {
            float e[4][4] = {{0.f,0.f,0.f,0.f},{0.f,0.f,0.f,0.f},
                             {0.f,0.f,0.f,0.f},{0.f,0.f,0.f,0.f}};
            #pragma unroll
            for (int i = 0; i < 6; i++) {
                uint32_t b0[4], b1[4];
                uint32_t tb = sbase + SB_T + (uint32_t)(((kh*6 + i)*16)*40)*2 + ldsm40;
                LDSM4T(b0, tb);
                LDSM4T(b1, tb + 32);
                MMA16816(e[0], wf[i], b0[0], b0[1]);
                MMA16816(e[1], wf[i], b0[2], b0[3]);
                MMA16816(e[2], wf[i], b1[0], b1[1]);
                MMA16816(e[3], wf[i], b1[2], b1[3]);
            }
            float* U = Uf + kh*2176;
            #pragma unroll
            for (int j = 0; j < 4; j++) {
                int w0 = j*8 + tq*2;
                int c0 = r_s2*16 + group;
                U[w0*68 + c0]           = e[j][0];
                U[(w0 + 1)*68 + c0]     = e[j][1];
                U[w0*68 + c0 + 8]       = e[j][2];
                U[(w0 + 1)*68 + c0 + 8] = e[j][3];
            }
        }
        __syncthreads();

        // ---- epilogue ----
        {
            int l = l0 + lt;
            float cnt = (float)((l + 1 < KW_) ? (l + 1) : KW_);
            __half* ug = g_u2h + (size_t)(n*L_ + l)*(V_*CO_);
            for (int j = tid; j < V_*CO_; j += 256) {
                int w = j >> 6, c = j & 63;          // c == myc
                float val = Uf[w*68 + c] + Uf[2176 + w*68 + c] + cnt*BF[w*64 + c];
                csum  += val;
                csum2 += val*val;
                ug[j] = __float2half(val);
            }
        }
    }

    float* st = (float*)(sm + SB_ST);
    atomicAdd(&st[myc], csum);
    atomicAdd(&st[64 + myc], csum2);
    __syncthreads();
    if (tid < CO_) {
        atomicAdd(&g_sum[tid],   st[tid]);
        atomicAdd(&g_sumsq[tid], st[64 + tid]);
    }
}

// ---------------- k3z: finalize BN stats + re-zero accumulators ----------------
__global__ void k3z(const float* __restrict__ gamma, const float* __restrict__ beta) {
    int c = threadIdx.x;
    if (c < CO_) {
        const float cnt = (float)(N_*L_*V_);
        float mean = g_sum[c] / cnt;
        float var  = g_sumsq[c] / cnt - mean*mean;
        float inv  = rsqrtf(var + 1e-5f);
        float sc   = gamma[c]*inv;
        g_scale[c] = sc;
        g_shift[c] = beta[c] - mean*sc;
        g_sum[c] = 0.f;                 // ready for next graph replay
        g_sumsq[c] = 0.f;
    }
}

// ---------------- k4: transpose + BN + relu + residual + relu ----------------
#define K4_SMEM (200*65*4)
__global__ void __launch_bounds__(512) k4_out(const float* __restrict__ x,
                                              float* __restrict__ out) {
    extern __shared__ float sm4[];
    __shared__ float s_sc[64], s_sh[64];
    int tid = threadIdx.x;
    int n = blockIdx.y, l0 = blockIdx.x * 8;

    if (tid < CO_) { s_sc[tid] = g_scale[tid]; s_sh[tid] = g_shift[tid]; }

    {   // fp16 u2 tile -> fp32 smem [200 rows (l,w)][ld 65]
        const __half2* src = (const __half2*)(g_u2h + (size_t)(n*L_ + l0)*(V_*CO_));
        for (int i = tid; i < 8*V_*CO_/2; i += 512) {
            float2 uv = __half22float2(src[i]);
            int rr = i >> 5, c = (i & 31)*2;
            sm4[rr*65 + c]     = uv.x;
            sm4[rr*65 + c + 1] = uv.y;
        }
    }
    __syncthreads();

    {   // fixed channel per thread, fully unrolled for MLP
        int c = tid >> 3, rg = tid & 7;
        float sc = s_sc[c], sh = s_sh[c];
        const float* xc = x   + ((size_t)(n*CO_ + c)*L_ + l0)*V_;
        float*       oc = out + ((size_t)(n*CO_ + c)*L_ + l0)*V_;
        float xv[V_];
        #pragma unroll
        for (int i = 0; i < V_; i++) xv[i] = xc[i*8 + rg];
        #pragma unroll
        for (int i = 0; i < V_; i++) {
            int rr = i*8 + rg;
            float val = sm4[rr*65 + c]*sc + sh;
            oc[rr] = fmaxf(fmaxf(val, 0.f) + xv[i], 0.f);
        }
    }
}

// ---------------- launch ----------------
extern "C" void kernel_launch(void* const* d_in, const int* in_sizes, int n_in,
                              void* d_out, int out_size) {
    const float* x     = (const float*)d_in[0];
    const float* A     = (const float*)d_in[1];
    const float* edge  = (const float*)d_in[2];
    const float* cw    = (const float*)d_in[3];
    const float* cb    = (const float*)d_in[4];
    const float* gamma = (const float*)d_in[5];
    const float* beta  = (const float*)d_in[6];
    float* out = (float*)d_out;

    cudaFuncSetAttribute(k2_fused, cudaFuncAttributeMaxDynamicSharedMemorySize, SB_TOTAL);
    cudaFuncSetAttribute(k4_out,   cudaFuncAttributeMaxDynamicSharedMemorySize, K4_SMEM);

    k2_fused<<<dim3(L_/LT_, N_), 256, SB_TOTAL>>>(x, A, edge, cw, cb);
    k3z<<<1, 64>>>(gamma, beta);
    k4_out<<<dim3(L_/8, N_), 512, K4_SMEM>>>(x, out);
}

// round 16
// speedup vs baseline: 1.2235x; 1.2235x over previous
#include <cuda_runtime.h>
#include <cuda_fp16.h>
#include <cstdint>

#define N_ 4
#define CI_ 64
#define CO_ 64
#define L_ 1024
#define V_ 25
#define P_ 3
#define VP_ 32
#define KW_ 9
#define K2_ 192
#define LT_ 4

// ---------------- scratch (__device__ globals) ----------------
__device__ __align__(16) __half g_u2h[N_*L_*V_*CO_];  // [n][l][w25][c] pre-BN (fp16)
__device__ __align__(16) __half g_W2h[64*200];        // [c64][200]  (k=p*64+ci, pad)
__device__ __align__(16) __half g_Aeh[96*40];         // [(p,v)96][40w]
__device__ float  g_bf2[VP_*CO_];                     // [w32][c64]
__device__ float  g_sum[CO_], g_sumsq[CO_];

// ---------------- PTX primitives ----------------
__device__ __forceinline__ uint32_t smem_u32(const void* p) {
    uint32_t a;
    asm("{ .reg .u64 t; cvta.to.shared.u64 t, %1; cvt.u32.u64 %0, t; }" : "=r"(a) : "l"(p));
    return a;
}
#define LDSM4(r, addr) \
    asm volatile("ldmatrix.sync.aligned.m8n8.x4.shared.b16 {%0,%1,%2,%3}, [%4];" \
        : "=r"((r)[0]), "=r"((r)[1]), "=r"((r)[2]), "=r"((r)[3]) : "r"(addr))
#define LDSM4T(r, addr) \
    asm volatile("ldmatrix.sync.aligned.m8n8.x4.trans.shared.b16 {%0,%1,%2,%3}, [%4];" \
        : "=r"((r)[0]), "=r"((r)[1]), "=r"((r)[2]), "=r"((r)[3]) : "r"(addr))
#define MMA16816(d, a, b0, b1) \
    asm volatile("mma.sync.aligned.m16n8k16.row.col.f32.f16.f16.f32 " \
        "{%0,%1,%2,%3}, {%4,%5,%6,%7}, {%8,%9}, {%0,%1,%2,%3};" \
        : "+f"((d)[0]), "+f"((d)[1]), "+f"((d)[2]), "+f"((d)[3]) \
        : "r"((a)[0]), "r"((a)[1]), "r"((a)[2]), "r"((a)[3]), "r"(b0), "r"(b1))

// ---------------- k0: fold weights into fp16 / final layouts (WIDE launch) --------
__global__ void k0_prep(const float* __restrict__ A, const float* __restrict__ edge,
                        const float* __restrict__ cw, const float* __restrict__ cb) {
    int tid = threadIdx.x + blockIdx.x * blockDim.x;
    int nth = blockDim.x * gridDim.x;
    for (int i = tid; i < 64*200; i += nth) {
        int c = i / 200, k = i % 200;
        float val = 0.f;
        if (k < K2_) { int p = k >> 6, ci = k & 63; val = cw[(p*CO_ + c)*CI_ + ci]; }
        g_W2h[i] = __float2half(val);
    }
    for (int i = tid; i < 96*40; i += nth) {
        int row = i / 40, w = i % 40, p = row >> 5, v = row & 31;
        float val = 0.f;
        if (v < V_ && w < V_) { int j = (p*V_ + v)*V_ + w; val = A[j]*edge[j]; }
        g_Aeh[i] = __float2half(val);
    }
    for (int i = tid; i < VP_*CO_; i += nth) {
        int w = i >> 6, c = i & 63;
        float s = 0.f;
        if (w < V_)
            for (int p = 0; p < P_; p++) {
                float col = 0.f;
                for (int v = 0; v < V_; v++) { int j = (p*V_+v)*V_+w; col += A[j]*edge[j]; }
                s += cb[p*CO_ + c]*col;
            }
        g_bf2[i] = s;
    }
    if (tid < CO_) { g_sum[tid] = 0.f; g_sumsq[tid] = 0.f; }
}

// ---------------- k2: fused presum + double fp16 GEMM, 3 blocks/SM ----------------
#define SB_XS 0                         // half [256(lt,ci)][40v]    20480
#define SB_T  20480                     // half [192k][40w]          15360
#define SB_AE 35840                     // half [96(p,v)][40w]        7680
#define SB_U  43520                     // f32 2kh x [32w][68 c-ld]  17408
#define SB_BF 60928                     // f32 [32w][64c]             8192
#define SB_ST 69120                     // f32 stats 128               512
#define SB_TOTAL 69632                  // 68 KB -> 3 blocks/SM

__global__ void __launch_bounds__(256, 3) k2_fused(const float* __restrict__ x) {
    extern __shared__ char sm[];
    const uint32_t sbase = smem_u32(sm);
    int tid = threadIdx.x, ww = tid >> 5, lane = tid & 31;
    int n = blockIdx.y, l0 = blockIdx.x * LT_;
    const int group = lane >> 2, tq = lane & 3;

    const uint32_t ldsm40  = ((lane & 7) + ((lane >> 3) & 1) * 8) * 80
                           + ((lane >> 4) & 1) * 16;
    const uint32_t ldsm200 = ((lane & 7) + ((lane >> 3) & 1) * 8) * 400
                           + ((lane >> 4) & 1) * 16;

    // ---- phase 0: stage W2 transiently; load BF; zero stats ----
    {
        const float4* wsrc = (const float4*)g_W2h;
        float4* wdst = (float4*)sm;
        for (int i = tid; i < 3200; i += 256) wdst[i] = wsrc[i];
        const float4* bsrc = (const float4*)g_bf2;
        float4* bdst = (float4*)(sm + SB_BF);
        for (int i = tid; i < 512; i += 256) bdst[i] = bsrc[i];
        float* st = (float*)(sm + SB_ST);
        if (tid < 128) st[tid] = 0.f;
    }
    __syncthreads();

    // ---- phase 1: cache this warp's stage-2 A fragments (24 regs) ----
    const int r_s2 = ww & 3;
    const int kh   = ww >> 2;
    uint32_t wf[6][4];
    #pragma unroll
    for (int i = 0; i < 6; i++)
        LDSM4(wf[i], sbase + (uint32_t)((r_s2*16)*200 + (kh*6 + i)*16)*2 + ldsm200);
    __syncthreads();

    // ---- phase 2: AE copy + fused temporal presum -> XS (half) ----
    {
        const float4* asrc = (const float4*)g_Aeh;
        float4* adst = (float4*)(sm + SB_AE);
        for (int i = tid; i < 480; i += 256) adst[i] = asrc[i];
    }
    __half* xs = (__half*)(sm + SB_XS);
    for (int it = 0; it < 8; it++) {
        int pair = tid + it*256;
        int ci = pair >> 5, v = pair & 31;
        if (v >= V_) {
            #pragma unroll
            for (int j = 0; j < LT_; j++) xs[(j*64 + ci)*40 + v] = __float2half(0.f);
            continue;
        }
        const float* xb = x + ((size_t)(n*CI_ + ci)*L_)*V_ + v;
        float vals[KW_ - 1 + LT_];
        #pragma unroll
        for (int i = 0; i < KW_ - 1 + LT_; i++) {
            int l = l0 - (KW_ - 1) + i;
            vals[i] = (l >= 0) ? xb[(size_t)l*V_] : 0.f;
        }
        float s = 0.f;
        #pragma unroll
        for (int i = 0; i < KW_ - 1; i++) s += vals[i];
        #pragma unroll
        for (int j = 0; j < LT_; j++) {
            s += vals[j + KW_ - 1];
            xs[(j*64 + ci)*40 + v] = __float2half(s);
            s -= vals[j];
        }
    }
    __syncthreads();

    const int myc = tid & 63;
    float csum = 0.f, csum2 = 0.f;
    float* Uf = (float*)(sm + SB_U);
    const float* BF = (const float*)(sm + SB_BF);

    for (int lt = 0; lt < LT_; lt++) {
        // ---- stage 1 ----
        {
            int ct = ww & 3, h = ww >> 2;
            uint32_t a[2][4];
            #pragma unroll
            for (int ks = 0; ks < 2; ks++)
                LDSM4(a[ks], sbase + SB_XS
                      + (uint32_t)((lt*64 + ct*16)*40 + ks*16)*2 + ldsm40);
            #pragma unroll
            for (int q = 0; q < 3; q++) {
                int idx = h*3 + q, p = idx >> 1, wt = idx & 1;
                float d[2][4] = {{0.f,0.f,0.f,0.f},{0.f,0.f,0.f,0.f}};
                #pragma unroll
                for (int ks = 0; ks < 2; ks++) {
                    uint32_t b[4];
                    LDSM4T(b, sbase + SB_AE
                           + (uint32_t)((p*32 + ks*16)*40 + wt*16)*2 + ldsm40);
                    MMA16816(d[0], a[ks], b[0], b[1]);
                    MMA16816(d[1], a[ks], b[2], b[3]);
                }
                #pragma unroll
                for (int j = 0; j < 2; j++) {
                    int wcol = wt*16 + j*8 + tq*2;
                    int row  = p*64 + ct*16 + group;
                    *(__half2*)(sm + SB_T + (row*40 + wcol)*2)
                        = __floats2half2_rn(d[j][0], d[j][1]);
                    *(__half2*)(sm + SB_T + ((row + 8)*40 + wcol)*2)
                        = __floats2half2_rn(d[j][2], d[j][3]);
                }
            }
        }
        __syncthreads();

        // ---- stage 2 ----
        {
            float e[4][4] = {{0.f,0.f,0.f,0.f},{0.f,0.f,0.f,0.f},
                             {0.f,0.f,0.f,0.f},{0.f,0.f,0.f,0.f}};
            #pragma unroll
            for (int i = 0; i < 6; i++) {
                uint32_t b0[4], b1[4];
                uint32_t tb = sbase + SB_T + (uint32_t)(((kh*6 + i)*16)*40)*2 + ldsm40;
                LDSM4T(b0, tb);
                LDSM4T(b1, tb + 32);
                MMA16816(e[0], wf[i], b0[0], b0[1]);
                MMA16816(e[1], wf[i], b0[2], b0[3]);
                MMA16816(e[2], wf[i], b1[0], b1[1]);
                MMA16816(e[3], wf[i], b1[2], b1[3]);
            }
            float* U = Uf + kh*2176;
            #pragma unroll
            for (int j = 0; j < 4; j++) {
                int w0 = j*8 + tq*2;
                int c0 = r_s2*16 + group;
                U[w0*68 + c0]           = e[j][0];
                U[(w0 + 1)*68 + c0]     = e[j][1];
                U[w0*68 + c0 + 8]       = e[j][2];
                U[(w0 + 1)*68 + c0 + 8] = e[j][3];
            }
        }
        __syncthreads();

        // ---- epilogue ----
        {
            int l = l0 + lt;
            float cnt = (float)((l + 1 < KW_) ? (l + 1) : KW_);
            __half* ug = g_u2h + (size_t)(n*L_ + l)*(V_*CO_);
            for (int j = tid; j < V_*CO_; j += 256) {
                int w = j >> 6, c = j & 63;          // c == myc
                float val = Uf[w*68 + c] + Uf[2176 + w*68 + c] + cnt*BF[w*64 + c];
                csum  += val;
                csum2 += val*val;
                ug[j] = __float2half(val);
            }
        }
    }

    float* st = (float*)(sm + SB_ST);
    atomicAdd(&st[myc], csum);
    atomicAdd(&st[64 + myc], csum2);
    __syncthreads();
    if (tid < CO_) {
        atomicAdd(&g_sum[tid],   st[tid]);
        atomicAdd(&g_sumsq[tid], st[64 + tid]);
    }
}

// ---------------- k4: stats finalize + transpose + BN + relu + residual + relu ----
#define K4_SMEM (200*65*4)
__global__ void __launch_bounds__(512) k4_out(const float* __restrict__ x,
                                              const float* __restrict__ gamma,
                                              const float* __restrict__ beta,
                                              float* __restrict__ out) {
    extern __shared__ float sm4[];
    __shared__ float s_sc[64], s_sh[64];
    int tid = threadIdx.x;
    int n = blockIdx.y, l0 = blockIdx.x * 8;

    // prologue: finalize BN stats locally (no separate launch)
    if (tid < CO_) {
        const float cnt = (float)(N_*L_*V_);
        float mean = g_sum[tid] / cnt;
        float var  = g_sumsq[tid] / cnt - mean*mean;
        float inv  = rsqrtf(var + 1e-5f);
        float sc   = gamma[tid]*inv;
        s_sc[tid] = sc;
        s_sh[tid] = beta[tid] - mean*sc;
    }

    {   // fp16 u2 tile -> fp32 smem [200 rows (l,w)][ld 65]
        const __half2* src = (const __half2*)(g_u2h + (size_t)(n*L_ + l0)*(V_*CO_));
        for (int i = tid; i < 8*V_*CO_/2; i += 512) {
            float2 uv = __half22float2(src[i]);
            int rr = i >> 5, c = (i & 31)*2;
            sm4[rr*65 + c]     = uv.x;
            sm4[rr*65 + c + 1] = uv.y;
        }
    }
    __syncthreads();

    {   // fixed channel per thread, fully unrolled for MLP
        int c = tid >> 3, rg = tid & 7;
        float sc = s_sc[c], sh = s_sh[c];
        const float* xc = x   + ((size_t)(n*CO_ + c)*L_ + l0)*V_;
        float*       oc = out + ((size_t)(n*CO_ + c)*L_ + l0)*V_;
        float xv[V_];
        #pragma unroll
        for (int i = 0; i < V_; i++) xv[i] = xc[i*8 + rg];
        #pragma unroll
        for (int i = 0; i < V_; i++) {
            int rr = i*8 + rg;
            float val = sm4[rr*65 + c]*sc + sh;
            oc[rr] = fmaxf(fmaxf(val, 0.f) + xv[i], 0.f);
        }
    }
}

// ---------------- launch ----------------
extern "C" void kernel_launch(void* const* d_in, const int* in_sizes, int n_in,
                              void* d_out, int out_size) {
    const float* x     = (const float*)d_in[0];
    const float* A     = (const float*)d_in[1];
    const float* edge  = (const float*)d_in[2];
    const float* cw    = (const float*)d_in[3];
    const float* cb    = (const float*)d_in[4];
    const float* gamma = (const float*)d_in[5];
    const float* beta  = (const float*)d_in[6];
    float* out = (float*)d_out;

    cudaFuncSetAttribute(k2_fused, cudaFuncAttributeMaxDynamicSharedMemorySize, SB_TOTAL);
    cudaFuncSetAttribute(k4_out,   cudaFuncAttributeMaxDynamicSharedMemorySize, K4_SMEM);

    k0_prep<<<40, 256>>>(A, edge, cw, cb);     // wide launch: latency, not loops
    k2_fused<<<dim3(L_/LT_, N_), 256, SB_TOTAL>>>(x);
    k4_out<<<dim3(L_/8, N_), 512, K4_SMEM>>>(x, gamma, beta, out);
}